// round 2
// baseline (speedup 1.0000x reference)
#include <cuda_runtime.h>
#include <cuda_bf16.h>

#define NROWS 4096            // batch rows (2*2048)
#define NFEAT 16384           // 128*128
#define LDW 136               // padded smem leading dim (bf16 elems), conflict-free for ldmatrix
#define DSTRIDE ((size_t)128 * 4096)
#define SMEM_BYTES (4 * 128 * LDW * 2 + 128 * 4)

// Scratch (allocation-free requirement): two 256MB ping-pong buffers.
__device__ float g_bufA[67108864];
__device__ float g_bufB[67108864];

// ---------------------------------------------------------------------------
// 2D transpose: dst[c*rows + r] = src[r*cols + c]
// ---------------------------------------------------------------------------
__global__ void transpose_k(float* __restrict__ dst, const float* __restrict__ src,
                            int rows, int cols) {
    __shared__ float t[32][33];
    int c0 = blockIdx.x * 32, r0 = blockIdx.y * 32;
    int tx = threadIdx.x, ty = threadIdx.y;
#pragma unroll
    for (int i = 0; i < 32; i += 8)
        t[ty + i][tx] = src[(size_t)(r0 + ty + i) * cols + (c0 + tx)];
    __syncthreads();
#pragma unroll
    for (int i = 0; i < 32; i += 8)
        dst[(size_t)(c0 + ty + i) * rows + (r0 + tx)] = t[tx][ty + i];
}

// ---------------------------------------------------------------------------
// MMA helpers (Ampere-style mma.sync, bf16 in / f32 accumulate)
// ---------------------------------------------------------------------------
__device__ __forceinline__ void ldsm4(unsigned r[4], const __nv_bfloat16* p) {
    unsigned a = (unsigned)__cvta_generic_to_shared(p);
    asm volatile("ldmatrix.sync.aligned.m8n8.x4.shared.b16 {%0,%1,%2,%3}, [%4];"
                 : "=r"(r[0]), "=r"(r[1]), "=r"(r[2]), "=r"(r[3]) : "r"(a));
}
__device__ __forceinline__ void ldsm4t(unsigned r[4], const __nv_bfloat16* p) {
    unsigned a = (unsigned)__cvta_generic_to_shared(p);
    asm volatile("ldmatrix.sync.aligned.m8n8.x4.trans.shared.b16 {%0,%1,%2,%3}, [%4];"
                 : "=r"(r[0]), "=r"(r[1]), "=r"(r[2]), "=r"(r[3]) : "r"(a));
}
__device__ __forceinline__ void mma16816(float c[4], const unsigned a[4],
                                         unsigned b0, unsigned b1) {
    asm volatile("mma.sync.aligned.m16n8k16.row.col.f32.bf16.bf16.f32 "
                 "{%0,%1,%2,%3}, {%4,%5,%6,%7}, {%8,%9}, {%0,%1,%2,%3};"
                 : "+f"(c[0]), "+f"(c[1]), "+f"(c[2]), "+f"(c[3])
                 : "r"(a[0]), "r"(a[1]), "r"(a[2]), "r"(a[3]), "r"(b0), "r"(b1));
}

// fp32 -> (bf16 hi, bf16 lo) split, store 4 consecutive elems
__device__ __forceinline__ void split_store4(__nv_bfloat16* ph, __nv_bfloat16* pl, float4 v) {
    float vv[4] = {v.x, v.y, v.z, v.w};
    __nv_bfloat16 h[4], l[4];
#pragma unroll
    for (int i = 0; i < 4; ++i) {
        h[i] = __float2bfloat16_rn(vv[i]);
        float rr = vv[i] - __bfloat162float(h[i]);
        l[i] = __float2bfloat16_rn(rr);
    }
    __nv_bfloat162 h01; h01.x = h[0]; h01.y = h[1];
    __nv_bfloat162 h23; h23.x = h[2]; h23.y = h[3];
    __nv_bfloat162 l01; l01.x = l[0]; l01.y = l[1];
    __nv_bfloat162 l23; l23.x = l[2]; l23.y = l[3];
    ((__nv_bfloat162*)ph)[0] = h01; ((__nv_bfloat162*)ph)[1] = h23;
    ((__nv_bfloat162*)pl)[0] = l01; ((__nv_bfloat162*)pl)[1] = l23;
}

// ---------------------------------------------------------------------------
// GEMM stage (r-major): for block blk, D[n][r] = sum_m W[blk,n,m] * B[m][r]
//  stage 1: B rows = xt[(m*128+blk)][:],        D rows = z2[(n*128+blk)][:]
//  stage 2: B rows = z2[(blk*128+m)][:],        D rows = out2[(n*128+blk)][:] + bias[n*128+blk]
// CTA tile: 128(n) x 128(r), K = 128 fully in smem. bf16x3 (hi/lo split).
// ---------------------------------------------------------------------------
__global__ void __launch_bounds__(256)
gemm_k(float* __restrict__ dst, const float* __restrict__ bmat,
       const float* __restrict__ wmat, const float* __restrict__ bias, int stage) {
    extern __shared__ unsigned char smem_raw[];
    __nv_bfloat16* whi = (__nv_bfloat16*)smem_raw;
    __nv_bfloat16* wlo = whi + 128 * LDW;
    __nv_bfloat16* bhi = wlo + 128 * LDW;
    __nv_bfloat16* blo = bhi + 128 * LDW;
    float* bias_s = (float*)(blo + 128 * LDW);

    const int blk = blockIdx.y;
    const int r0  = blockIdx.x * 128;
    const int tid = threadIdx.x;

    const float* W = wmat + (size_t)blk * 16384;
    const float* B;
    size_t bstride;
    if (stage == 1) { B = bmat + (size_t)blk * 4096;        bstride = DSTRIDE; }
    else            { B = bmat + (size_t)blk * DSTRIDE;     bstride = 4096;    }
    float* D = dst + (size_t)blk * 4096;

    if (tid < 128)
        bias_s[tid] = (stage == 2) ? bias[(size_t)tid * 128 + blk] : 0.0f;

    // ---- load W (128x128 f32) -> split bf16 hi/lo in smem [n][m], ld=LDW
#pragma unroll
    for (int it = 0; it < 16; ++it) {
        int idx = it * 256 + tid;        // 0..4095 float4s
        int n = idx >> 5, mq = idx & 31;
        float4 v = *(const float4*)(W + (size_t)n * 128 + mq * 4);
        split_store4(whi + n * LDW + mq * 4, wlo + n * LDW + mq * 4, v);
    }
    // ---- load B tile (128 k-rows x 128 r) -> split bf16 [k][r], ld=LDW
#pragma unroll
    for (int it = 0; it < 16; ++it) {
        int idx = it * 256 + tid;
        int k = idx >> 5, rq = idx & 31;
        float4 v = *(const float4*)(B + (size_t)k * bstride + r0 + rq * 4);
        split_store4(bhi + k * LDW + rq * 4, blo + k * LDW + rq * 4, v);
    }
    __syncthreads();

    // ---- compute: 8 warps, warp tile 64(n) x 32(r)
    const int wid = tid >> 5, lane = tid & 31;
    const int wm = (wid & 1) * 64;      // n offset
    const int wr = (wid >> 1) * 32;     // r offset
    const int lrow  = lane & 15;
    const int lcol8 = (lane >> 4) << 3;

    float acc[4][4][4];
#pragma unroll
    for (int a = 0; a < 4; ++a)
#pragma unroll
        for (int b = 0; b < 4; ++b)
#pragma unroll
            for (int c = 0; c < 4; ++c) acc[a][b][c] = 0.0f;

#pragma unroll
    for (int k0 = 0; k0 < 128; k0 += 16) {
        unsigned Ah[4][4], Al[4][4], Bh[2][4], Bl[2][4];
#pragma unroll
        for (int mt = 0; mt < 4; ++mt) {
            const int nrow = wm + mt * 16 + lrow;
            ldsm4(Ah[mt], whi + nrow * LDW + k0 + lcol8);
            ldsm4(Al[mt], wlo + nrow * LDW + k0 + lcol8);
        }
#pragma unroll
        for (int h = 0; h < 2; ++h) {
            const int coff = wr + h * 16 + lcol8;
            ldsm4t(Bh[h], bhi + (k0 + lrow) * LDW + coff);
            ldsm4t(Bl[h], blo + (k0 + lrow) * LDW + coff);
        }
#pragma unroll
        for (int mt = 0; mt < 4; ++mt)
#pragma unroll
            for (int rt = 0; rt < 4; ++rt) {
                const int h = rt >> 1, p = (rt & 1) * 2;
                mma16816(acc[mt][rt], Ah[mt], Bh[h][p], Bh[h][p + 1]);  // hi*hi
                mma16816(acc[mt][rt], Ah[mt], Bl[h][p], Bl[h][p + 1]);  // hi*lo
                mma16816(acc[mt][rt], Al[mt], Bh[h][p], Bh[h][p + 1]);  // lo*hi
            }
    }

    // ---- epilogue: D[n][r] (+bias per n), rows strided DSTRIDE
    const int erow = lane >> 2;
    const int ecol = (lane & 3) * 2;
#pragma unroll
    for (int mt = 0; mt < 4; ++mt)
#pragma unroll
        for (int rt = 0; rt < 4; ++rt) {
            const int n0 = wm + mt * 16 + erow;
            const int rr = r0 + wr + rt * 8 + ecol;
            const float bv0 = bias_s[n0];
            const float bv1 = bias_s[n0 + 8];
            float2 o0 = make_float2(acc[mt][rt][0] + bv0, acc[mt][rt][1] + bv0);
            float2 o1 = make_float2(acc[mt][rt][2] + bv1, acc[mt][rt][3] + bv1);
            *(float2*)(D + (size_t)n0 * DSTRIDE + rr)       = o0;
            *(float2*)(D + (size_t)(n0 + 8) * DSTRIDE + rr) = o1;
        }
}

// ---------------------------------------------------------------------------
extern "C" void kernel_launch(void* const* d_in, const int* in_sizes, int n_in,
                              void* d_out, int out_size) {
    const float* x    = (const float*)d_in[0];
    const float* L    = (const float*)d_in[1];
    const float* R    = (const float*)d_in[2];
    const float* bias = (const float*)d_in[3];
    float* out = (float*)d_out;

    float *bufA, *bufB;
    cudaGetSymbolAddress((void**)&bufA, g_bufA);
    cudaGetSymbolAddress((void**)&bufB, g_bufB);
    cudaFuncSetAttribute(gemm_k, cudaFuncAttributeMaxDynamicSharedMemorySize, SMEM_BYTES);

    // 1) xt[c][r] = x[r][c]   (r-major conversion; absorbs perm #1 into row indexing)
    transpose_k<<<dim3(NFEAT / 32, NROWS / 32), dim3(32, 8)>>>(bufA, x, NROWS, NFEAT);
    // 2) z2[(n*128+b)][r] = sum_m L[b,n,m] * xt[(m*128+b)][r]
    gemm_k<<<dim3(NROWS / 128, 128), 256, SMEM_BYTES>>>(bufB, bufA, L, nullptr, 1);
    // 3) out2[(i*128+j)][r] = sum_m R[j,i,m] * z2[(j*128+m)][r] + bias[i*128+j]
    gemm_k<<<dim3(NROWS / 128, 128), 256, SMEM_BYTES>>>(bufA, bufB, R, bias, 2);
    // 4) out[r][c] = out2[c][r]   (absorbs perm #3)
    transpose_k<<<dim3(NROWS / 32, NFEAT / 32), dim3(32, 8)>>>(out, bufA, NFEAT, NROWS);
}

// round 4
// speedup vs baseline: 1.2077x; 1.2077x over previous
#include <cuda_runtime.h>
#include <cuda_bf16.h>

#define NROWS 4096            // batch rows (2*2048)
#define NFEAT 16384           // 128*128
#define LDB 136               // B-plane smem ld (bf16): 272B row stride, ldmatrix conflict-free
#define LDWW 72               // W-plane smem ld (bf16): 144B row stride, ldmatrix conflict-free
#define DSTRIDE ((size_t)128 * 4096)
// smem: Whi/Wlo 128x72, Bhi/Blo 64x136 (bf16), bias 128 f32
#define SMEM_BYTES ((2 * 128 * LDWW + 2 * 64 * LDB) * 2 + 128 * 4)

// Scratch (allocation-free requirement): two 256MB ping-pong buffers.
__device__ float g_bufA[67108864];
__device__ float g_bufB[67108864];

// ---------------------------------------------------------------------------
// 2D transpose: dst[c*rows + r] = src[r*cols + c]
// ---------------------------------------------------------------------------
__global__ void transpose_k(float* __restrict__ dst, const float* __restrict__ src,
                            int rows, int cols) {
    __shared__ float t[32][33];
    int c0 = blockIdx.x * 32, r0 = blockIdx.y * 32;
    int tx = threadIdx.x, ty = threadIdx.y;
#pragma unroll
    for (int i = 0; i < 32; i += 8)
        t[ty + i][tx] = src[(size_t)(r0 + ty + i) * cols + (c0 + tx)];
    __syncthreads();
#pragma unroll
    for (int i = 0; i < 32; i += 8)
        dst[(size_t)(c0 + ty + i) * rows + (r0 + tx)] = t[tx][ty + i];
}

// ---------------------------------------------------------------------------
// MMA helpers (mma.sync, bf16 in / f32 accumulate)
// ---------------------------------------------------------------------------
__device__ __forceinline__ void ldsm4(unsigned r[4], const __nv_bfloat16* p) {
    unsigned a = (unsigned)__cvta_generic_to_shared(p);
    asm volatile("ldmatrix.sync.aligned.m8n8.x4.shared.b16 {%0,%1,%2,%3}, [%4];"
                 : "=r"(r[0]), "=r"(r[1]), "=r"(r[2]), "=r"(r[3]) : "r"(a));
}
__device__ __forceinline__ void ldsm4t(unsigned r[4], const __nv_bfloat16* p) {
    unsigned a = (unsigned)__cvta_generic_to_shared(p);
    asm volatile("ldmatrix.sync.aligned.m8n8.x4.trans.shared.b16 {%0,%1,%2,%3}, [%4];"
                 : "=r"(r[0]), "=r"(r[1]), "=r"(r[2]), "=r"(r[3]) : "r"(a));
}
__device__ __forceinline__ void mma16816(float c[4], const unsigned a[4],
                                         unsigned b0, unsigned b1) {
    asm volatile("mma.sync.aligned.m16n8k16.row.col.f32.bf16.bf16.f32 "
                 "{%0,%1,%2,%3}, {%4,%5,%6,%7}, {%8,%9}, {%0,%1,%2,%3};"
                 : "+f"(c[0]), "+f"(c[1]), "+f"(c[2]), "+f"(c[3])
                 : "r"(a[0]), "r"(a[1]), "r"(a[2]), "r"(a[3]), "r"(b0), "r"(b1));
}

// fp32 -> (bf16 hi, bf16 lo) split, store 4 consecutive elems
__device__ __forceinline__ void split_store4(__nv_bfloat16* ph, __nv_bfloat16* pl, float4 v) {
    float vv[4] = {v.x, v.y, v.z, v.w};
    __nv_bfloat16 h[4], l[4];
#pragma unroll
    for (int i = 0; i < 4; ++i) {
        h[i] = __float2bfloat16_rn(vv[i]);
        float rr = vv[i] - __bfloat162float(h[i]);
        l[i] = __float2bfloat16_rn(rr);
    }
    __nv_bfloat162 h01; h01.x = h[0]; h01.y = h[1];
    __nv_bfloat162 h23; h23.x = h[2]; h23.y = h[3];
    __nv_bfloat162 l01; l01.x = l[0]; l01.y = l[1];
    __nv_bfloat162 l23; l23.x = l[2]; l23.y = l[3];
    ((__nv_bfloat162*)ph)[0] = h01; ((__nv_bfloat162*)ph)[1] = h23;
    ((__nv_bfloat162*)pl)[0] = l01; ((__nv_bfloat162*)pl)[1] = l23;
}

// ---------------------------------------------------------------------------
// GEMM stage (r-major): for block blk, D[n][r] = sum_m W[blk,n,m] * B[m][r]
//  stage 1: B rows = xt[(m*128+blk)][:],   D rows = z2[(n*128+blk)][:]
//  stage 2: B rows = z2[(blk*128+m)][:],   D rows = out2[(n*128+blk)][:] + bias
// CTA tile: 128(n) x 128(r). K streamed in 2 chunks of 64 (smem 70.5KB ->
// 2 CTAs/SM so load and MMA phases of co-resident CTAs overlap). bf16x3 split.
// ---------------------------------------------------------------------------
__global__ void __launch_bounds__(256, 2)
gemm_k(float* __restrict__ dst, const float* __restrict__ bmat,
       const float* __restrict__ wmat, const float* __restrict__ bias, int stage) {
    extern __shared__ unsigned char smem_raw[];
    __nv_bfloat16* whi = (__nv_bfloat16*)smem_raw;                 // [128][LDWW]
    __nv_bfloat16* wlo = whi + 128 * LDWW;
    __nv_bfloat16* bhi = wlo + 128 * LDWW;                         // [64][LDB]
    __nv_bfloat16* blo = bhi + 64 * LDB;
    float* bias_s = (float*)(blo + 64 * LDB);

    const int blk = blockIdx.y;
    const int r0  = blockIdx.x * 128;
    const int tid = threadIdx.x;

    const float* W = wmat + (size_t)blk * 16384;
    const float* B;
    size_t bstride;
    if (stage == 1) { B = bmat + (size_t)blk * 4096;        bstride = DSTRIDE; }
    else            { B = bmat + (size_t)blk * DSTRIDE;     bstride = 4096;    }
    float* D = dst + (size_t)blk * 4096;

    if (tid < 128)
        bias_s[tid] = (stage == 2) ? bias[(size_t)tid * 128 + blk] : 0.0f;

    const int wid = tid >> 5, lane = tid & 31;
    const int wm = (wid & 1) * 64;      // n offset
    const int wr = (wid >> 1) * 32;     // r offset
    const int lrow  = lane & 15;
    const int lcol8 = (lane >> 4) << 3;

    float acc[4][4][4];
#pragma unroll
    for (int a = 0; a < 4; ++a)
#pragma unroll
        for (int b = 0; b < 4; ++b)
#pragma unroll
            for (int c = 0; c < 4; ++c) acc[a][b][c] = 0.0f;

    for (int kc = 0; kc < 2; ++kc) {
        __syncthreads();   // previous chunk's compute done before overwrite
        // ---- W chunk: 128 n x 64 k f32 -> bf16 hi/lo [n][k], ld=LDWW
#pragma unroll
        for (int it = 0; it < 8; ++it) {
            int idx = it * 256 + tid;        // 0..2047 float4s
            int n = idx >> 4, kq = idx & 15;
            float4 v = *(const float4*)(W + (size_t)n * 128 + kc * 64 + kq * 4);
            split_store4(whi + n * LDWW + kq * 4, wlo + n * LDWW + kq * 4, v);
        }
        // ---- B chunk: 64 k x 128 r f32 -> bf16 hi/lo [k][r], ld=LDB
#pragma unroll
        for (int it = 0; it < 8; ++it) {
            int idx = it * 256 + tid;
            int k = idx >> 5, rq = idx & 31;
            float4 v = *(const float4*)(B + (size_t)(kc * 64 + k) * bstride + r0 + rq * 4);
            split_store4(bhi + k * LDB + rq * 4, blo + k * LDB + rq * 4, v);
        }
        __syncthreads();

        // ---- compute: 8 warps, warp tile 64(n) x 32(r), 4 ksteps of 16
#pragma unroll
        for (int k0 = 0; k0 < 64; k0 += 16) {
            unsigned Ah[4][4], Al[4][4], Bh[2][4], Bl[2][4];
#pragma unroll
            for (int mt = 0; mt < 4; ++mt) {
                const int nrow = wm + mt * 16 + lrow;
                ldsm4(Ah[mt], whi + nrow * LDWW + k0 + lcol8);
                ldsm4(Al[mt], wlo + nrow * LDWW + k0 + lcol8);
            }
#pragma unroll
            for (int h = 0; h < 2; ++h) {
                const int coff = wr + h * 16 + lcol8;
                ldsm4t(Bh[h], bhi + (k0 + lrow) * LDB + coff);
                ldsm4t(Bl[h], blo + (k0 + lrow) * LDB + coff);
            }
#pragma unroll
            for (int mt = 0; mt < 4; ++mt)
#pragma unroll
                for (int rt = 0; rt < 4; ++rt) {
                    const int h = rt >> 1, p = (rt & 1) * 2;
                    mma16816(acc[mt][rt], Ah[mt], Bh[h][p], Bh[h][p + 1]);  // hi*hi
                    mma16816(acc[mt][rt], Ah[mt], Bl[h][p], Bl[h][p + 1]);  // hi*lo
                    mma16816(acc[mt][rt], Al[mt], Bh[h][p], Bh[h][p + 1]);  // lo*hi
                }
        }
    }

    // ---- epilogue: D[n][r] (+bias per n), rows strided DSTRIDE
    const int erow = lane >> 2;
    const int ecol = (lane & 3) * 2;
#pragma unroll
    for (int mt = 0; mt < 4; ++mt)
#pragma unroll
        for (int rt = 0; rt < 4; ++rt) {
            const int n0 = wm + mt * 16 + erow;
            const int rr = r0 + wr + rt * 8 + ecol;
            const float bv0 = bias_s[n0];
            const float bv1 = bias_s[n0 + 8];
            float2 o0 = make_float2(acc[mt][rt][0] + bv0, acc[mt][rt][1] + bv0);
            float2 o1 = make_float2(acc[mt][rt][2] + bv1, acc[mt][rt][3] + bv1);
            *(float2*)(D + (size_t)n0 * DSTRIDE + rr)       = o0;
            *(float2*)(D + (size_t)(n0 + 8) * DSTRIDE + rr) = o1;
        }
}

// ---------------------------------------------------------------------------
extern "C" void kernel_launch(void* const* d_in, const int* in_sizes, int n_in,
                              void* d_out, int out_size) {
    const float* x    = (const float*)d_in[0];
    const float* L    = (const float*)d_in[1];
    const float* R    = (const float*)d_in[2];
    const float* bias = (const float*)d_in[3];
    float* out = (float*)d_out;

    float *bufA, *bufB;
    cudaGetSymbolAddress((void**)&bufA, g_bufA);
    cudaGetSymbolAddress((void**)&bufB, g_bufB);
    cudaFuncSetAttribute(gemm_k, cudaFuncAttributeMaxDynamicSharedMemorySize, SMEM_BYTES);

    // 1) xt[c][r] = x[r][c]
    transpose_k<<<dim3(NFEAT / 32, NROWS / 32), dim3(32, 8)>>>(bufA, x, NROWS, NFEAT);
    // 2) z2[(n*128+b)][r] = sum_m L[b,n,m] * xt[(m*128+b)][r]
    gemm_k<<<dim3(NROWS / 128, 128), 256, SMEM_BYTES>>>(bufB, bufA, L, nullptr, 1);
    // 3) out2[(i*128+j)][r] = sum_m R[j,i,m] * z2[(j*128+m)][r] + bias
    gemm_k<<<dim3(NROWS / 128, 128), 256, SMEM_BYTES>>>(bufA, bufB, R, bias, 2);
    // 4) out[r][c] = out2[c][r]
    transpose_k<<<dim3(NROWS / 32, NFEAT / 32), dim3(32, 8)>>>(out, bufA, NFEAT, NROWS);
}

// round 5
// speedup vs baseline: 1.4840x; 1.2287x over previous
#include <cuda_runtime.h>
#include <cuda_fp16.h>

#define NROWS 4096            // batch rows (2*2048)
#define NFEAT 16384           // 128*128
#define LDB 136               // B-plane smem ld (fp16): 272B row stride, ldmatrix conflict-free
#define LDWW 72               // W-plane smem ld (fp16): 144B row stride, ldmatrix conflict-free
#define DSTRIDE ((size_t)128 * 4096)
// smem: W 128x72, B 64x136 (fp16), bias 128 f32
#define SMEM_BYTES ((128 * LDWW + 64 * LDB) * 2 + 128 * 4)

// Scratch (allocation-free requirement): two 256MB ping-pong buffers.
__device__ float g_bufA[67108864];
__device__ float g_bufB[67108864];

// ---------------------------------------------------------------------------
// 2D transpose, 64x64 tiles, float4 I/O: dst[c*rows + r] = src[r*cols + c]
// 256 threads: tx = tid&15 (x-quad), ty = tid>>4
// ---------------------------------------------------------------------------
__global__ void __launch_bounds__(256)
transpose_k(float* __restrict__ dst, const float* __restrict__ src,
            int rows, int cols) {
    __shared__ float t[64][65];
    const int c0 = blockIdx.x * 64, r0 = blockIdx.y * 64;
    const int tx = threadIdx.x & 15, ty = threadIdx.x >> 4;
#pragma unroll
    for (int k = 0; k < 4; ++k) {
        float4 v = *(const float4*)(src + (size_t)(r0 + ty + 16 * k) * cols + c0 + 4 * tx);
        t[ty + 16 * k][4 * tx + 0] = v.x;
        t[ty + 16 * k][4 * tx + 1] = v.y;
        t[ty + 16 * k][4 * tx + 2] = v.z;
        t[ty + 16 * k][4 * tx + 3] = v.w;
    }
    __syncthreads();
#pragma unroll
    for (int k = 0; k < 4; ++k) {
        float4 w;
        w.x = t[4 * tx + 0][ty + 16 * k];
        w.y = t[4 * tx + 1][ty + 16 * k];
        w.z = t[4 * tx + 2][ty + 16 * k];
        w.w = t[4 * tx + 3][ty + 16 * k];
        *(float4*)(dst + (size_t)(c0 + ty + 16 * k) * rows + r0 + 4 * tx) = w;
    }
}

// ---------------------------------------------------------------------------
// MMA helpers (mma.sync m16n8k16, fp16 in / f32 accumulate)
// ---------------------------------------------------------------------------
__device__ __forceinline__ void ldsm4(unsigned r[4], const __half* p) {
    unsigned a = (unsigned)__cvta_generic_to_shared(p);
    asm volatile("ldmatrix.sync.aligned.m8n8.x4.shared.b16 {%0,%1,%2,%3}, [%4];"
                 : "=r"(r[0]), "=r"(r[1]), "=r"(r[2]), "=r"(r[3]) : "r"(a));
}
__device__ __forceinline__ void ldsm4t(unsigned r[4], const __half* p) {
    unsigned a = (unsigned)__cvta_generic_to_shared(p);
    asm volatile("ldmatrix.sync.aligned.m8n8.x4.trans.shared.b16 {%0,%1,%2,%3}, [%4];"
                 : "=r"(r[0]), "=r"(r[1]), "=r"(r[2]), "=r"(r[3]) : "r"(a));
}
__device__ __forceinline__ void mma16816(float c[4], const unsigned a[4],
                                         unsigned b0, unsigned b1) {
    asm volatile("mma.sync.aligned.m16n8k16.row.col.f32.f16.f16.f32 "
                 "{%0,%1,%2,%3}, {%4,%5,%6,%7}, {%8,%9}, {%0,%1,%2,%3};"
                 : "+f"(c[0]), "+f"(c[1]), "+f"(c[2]), "+f"(c[3])
                 : "r"(a[0]), "r"(a[1]), "r"(a[2]), "r"(a[3]), "r"(b0), "r"(b1));
}

// fp32x4 -> fp16x4 store
__device__ __forceinline__ void h_store4(__half* p, float4 v) {
    __half2 a = __floats2half2_rn(v.x, v.y);
    __half2 b = __floats2half2_rn(v.z, v.w);
    ((__half2*)p)[0] = a;
    ((__half2*)p)[1] = b;
}

// ---------------------------------------------------------------------------
// GEMM stage (r-major): for block blk, D[n][r] = sum_m W[blk,n,m] * B[m][r]
//  stage 1: B rows = xt[(m*128+blk)][:],   D rows = z2[(n*128+blk)][:]
//  stage 2: B rows = z2[(blk*128+m)][:],   D rows = out2[(n*128+blk)][:] + bias
// CTA tile: 128(n) x 128(r). K streamed in 2 chunks of 64. fp16 single-pass
// (f32 accum). smem 36KB -> 2 CTAs/SM overlap load & MMA phases.
// ---------------------------------------------------------------------------
__global__ void __launch_bounds__(256, 2)
gemm_k(float* __restrict__ dst, const float* __restrict__ bmat,
       const float* __restrict__ wmat, const float* __restrict__ bias, int stage) {
    extern __shared__ unsigned char smem_raw[];
    __half* wsm = (__half*)smem_raw;                 // [128][LDWW]
    __half* bsm = wsm + 128 * LDWW;                  // [64][LDB]
    float* bias_s = (float*)(bsm + 64 * LDB);

    const int blk = blockIdx.y;
    const int r0  = blockIdx.x * 128;
    const int tid = threadIdx.x;

    const float* W = wmat + (size_t)blk * 16384;
    const float* B;
    size_t bstride;
    if (stage == 1) { B = bmat + (size_t)blk * 4096;        bstride = DSTRIDE; }
    else            { B = bmat + (size_t)blk * DSTRIDE;     bstride = 4096;    }
    float* D = dst + (size_t)blk * 4096;

    if (tid < 128)
        bias_s[tid] = (stage == 2) ? bias[(size_t)tid * 128 + blk] : 0.0f;

    const int wid = tid >> 5, lane = tid & 31;
    const int wm = (wid & 1) * 64;      // n offset
    const int wr = (wid >> 1) * 32;     // r offset
    const int lrow  = lane & 15;
    const int lcol8 = (lane >> 4) << 3;

    float acc[4][4][4];
#pragma unroll
    for (int a = 0; a < 4; ++a)
#pragma unroll
        for (int b = 0; b < 4; ++b)
#pragma unroll
            for (int c = 0; c < 4; ++c) acc[a][b][c] = 0.0f;

    for (int kc = 0; kc < 2; ++kc) {
        __syncthreads();   // previous chunk's compute done before overwrite
        // ---- W chunk: 128 n x 64 k f32 -> fp16 [n][k], ld=LDWW
#pragma unroll
        for (int it = 0; it < 8; ++it) {
            int idx = it * 256 + tid;        // 0..2047 float4s
            int n = idx >> 4, kq = idx & 15;
            float4 v = *(const float4*)(W + (size_t)n * 128 + kc * 64 + kq * 4);
            h_store4(wsm + n * LDWW + kq * 4, v);
        }
        // ---- B chunk: 64 k x 128 r f32 -> fp16 [k][r], ld=LDB
#pragma unroll
        for (int it = 0; it < 8; ++it) {
            int idx = it * 256 + tid;
            int k = idx >> 5, rq = idx & 31;
            float4 v = *(const float4*)(B + (size_t)(kc * 64 + k) * bstride + r0 + rq * 4);
            h_store4(bsm + k * LDB + rq * 4, v);
        }
        __syncthreads();

        // ---- compute: 8 warps, warp tile 64(n) x 32(r), 4 ksteps of 16
#pragma unroll
        for (int k0 = 0; k0 < 64; k0 += 16) {
            unsigned Ah[4][4], Bh[2][4];
#pragma unroll
            for (int mt = 0; mt < 4; ++mt)
                ldsm4(Ah[mt], wsm + (wm + mt * 16 + lrow) * LDWW + k0 + lcol8);
#pragma unroll
            for (int h = 0; h < 2; ++h)
                ldsm4t(Bh[h], bsm + (k0 + lrow) * LDB + wr + h * 16 + lcol8);
#pragma unroll
            for (int mt = 0; mt < 4; ++mt)
#pragma unroll
                for (int rt = 0; rt < 4; ++rt) {
                    const int h = rt >> 1, p = (rt & 1) * 2;
                    mma16816(acc[mt][rt], Ah[mt], Bh[h][p], Bh[h][p + 1]);
                }
        }
    }

    // ---- epilogue: D[n][r] (+bias per n), rows strided DSTRIDE
    const int erow = lane >> 2;
    const int ecol = (lane & 3) * 2;
#pragma unroll
    for (int mt = 0; mt < 4; ++mt)
#pragma unroll
        for (int rt = 0; rt < 4; ++rt) {
            const int n0 = wm + mt * 16 + erow;
            const int rr = r0 + wr + rt * 8 + ecol;
            const float bv0 = bias_s[n0];
            const float bv1 = bias_s[n0 + 8];
            float2 o0 = make_float2(acc[mt][rt][0] + bv0, acc[mt][rt][1] + bv0);
            float2 o1 = make_float2(acc[mt][rt][2] + bv1, acc[mt][rt][3] + bv1);
            *(float2*)(D + (size_t)n0 * DSTRIDE + rr)       = o0;
            *(float2*)(D + (size_t)(n0 + 8) * DSTRIDE + rr) = o1;
        }
}

// ---------------------------------------------------------------------------
extern "C" void kernel_launch(void* const* d_in, const int* in_sizes, int n_in,
                              void* d_out, int out_size) {
    const float* x    = (const float*)d_in[0];
    const float* L    = (const float*)d_in[1];
    const float* R    = (const float*)d_in[2];
    const float* bias = (const float*)d_in[3];
    float* out = (float*)d_out;

    float *bufA, *bufB;
    cudaGetSymbolAddress((void**)&bufA, g_bufA);
    cudaGetSymbolAddress((void**)&bufB, g_bufB);
    cudaFuncSetAttribute(gemm_k, cudaFuncAttributeMaxDynamicSharedMemorySize, SMEM_BYTES);

    // 1) xt[c][r] = x[r][c]
    transpose_k<<<dim3(NFEAT / 64, NROWS / 64), 256>>>(bufA, x, NROWS, NFEAT);
    // 2) z2[(n*128+b)][r] = sum_m L[b,n,m] * xt[(m*128+b)][r]
    gemm_k<<<dim3(NROWS / 128, 128), 256, SMEM_BYTES>>>(bufB, bufA, L, nullptr, 1);
    // 3) out2[(i*128+j)][r] = sum_m R[j,i,m] * z2[(j*128+m)][r] + bias
    gemm_k<<<dim3(NROWS / 128, 128), 256, SMEM_BYTES>>>(bufA, bufB, R, bias, 2);
    // 4) out[r][c] = out2[c][r]
    transpose_k<<<dim3(NROWS / 64, NFEAT / 64), 256>>>(out, bufA, NFEAT, NROWS);
}

// round 6
// speedup vs baseline: 2.2630x; 1.5249x over previous
#include <cuda_runtime.h>
#include <cuda_fp16.h>
#include <cstdint>

#define NROWS 4096            // batch rows (2*2048)
#define NFEAT 16384           // 128*128
#define LDB 136               // B-plane smem ld (fp16): 272B rows, ldmatrix conflict-free
#define LDWW 72               // W-plane smem ld (fp16): 144B rows, ldmatrix conflict-free
#define DSTRIDE ((size_t)128 * 4096)
#define WCH (128 * LDWW)      // halves per W chunk plane
#define BCH (64 * LDB)        // halves per B chunk plane
#define SMEM_BYTES (2 * (WCH + BCH) * 2)

// Scratch (allocation-free rule): ping-pong buffers (used as fp16) + W images.
__device__ float g_bufA[67108864];
__device__ float g_bufB[67108864];
__device__ __half g_wh[2][128 * 16384];   // fp16 W images, [which][blk][kc][n][kq]

__device__ __forceinline__ void cp16(uint32_t d, const void* s) {
    asm volatile("cp.async.cg.shared.global [%0], [%1], 16;" :: "r"(d), "l"(s));
}
#define CP_COMMIT() asm volatile("cp.async.commit_group;" ::: "memory")
#define CP_WAIT(n)  asm volatile("cp.async.wait_group %0;" :: "n"(n) : "memory")

// ---------------------------------------------------------------------------
// prep_w: L/R f32 -> fp16 images, chunk-major [blk][kc][n][kq] (kq in [0,64))
// ---------------------------------------------------------------------------
__global__ void prep_w_k(const float* __restrict__ L, const float* __restrict__ R) {
    const int which = blockIdx.y, blk = blockIdx.x, tid = threadIdx.x;
    const float* W = (which ? R : L) + (size_t)blk * 16384;
    __half* img = g_wh[which] + (size_t)blk * 16384;
#pragma unroll
    for (int it = 0; it < 16; ++it) {
        int idx = it * 256 + tid;            // 4096 float4s
        int n = idx >> 5, kq4 = idx & 31;    // k = 4*kq4
        float4 v = *(const float4*)(W + (size_t)n * 128 + kq4 * 4);
        int kc = kq4 >> 4;
        __half* d = img + kc * 8192 + n * 64 + (kq4 * 4 & 63);
        ((__half2*)d)[0] = __floats2half2_rn(v.x, v.y);
        ((__half2*)d)[1] = __floats2half2_rn(v.z, v.w);
    }
}

// ---------------------------------------------------------------------------
// T1: xt[c][r] (fp16) = x[r][c] (f32).  64x64 tiles.
// ---------------------------------------------------------------------------
__global__ void __launch_bounds__(256)
t1_k(__half* __restrict__ dst, const float* __restrict__ src) {
    __shared__ float t[64][65];
    const int c0 = blockIdx.x * 64, r0 = blockIdx.y * 64;
    const int tx = threadIdx.x & 15, ty = threadIdx.x >> 4;
#pragma unroll
    for (int k = 0; k < 4; ++k) {
        float4 v = *(const float4*)(src + (size_t)(r0 + ty + 16 * k) * NFEAT + c0 + 4 * tx);
        t[4 * tx + 0][ty + 16 * k] = v.x;
        t[4 * tx + 1][ty + 16 * k] = v.y;
        t[4 * tx + 2][ty + 16 * k] = v.z;
        t[4 * tx + 3][ty + 16 * k] = v.w;
    }
    __syncthreads();
#pragma unroll
    for (int k = 0; k < 4; ++k) {
        const int cl = ty + 16 * k;
        __half2 a = __floats2half2_rn(t[cl][4 * tx + 0], t[cl][4 * tx + 1]);
        __half2 b = __floats2half2_rn(t[cl][4 * tx + 2], t[cl][4 * tx + 3]);
        __half2* p = (__half2*)(dst + (size_t)(c0 + cl) * NROWS + r0 + 4 * tx);
        p[0] = a; p[1] = b;
    }
}

// ---------------------------------------------------------------------------
// T2: out[r][c] (f32) = out2[c][r] (fp16) + bias[c].  64x64 tiles.
// ---------------------------------------------------------------------------
__global__ void __launch_bounds__(256)
t2_k(float* __restrict__ dst, const __half* __restrict__ src,
     const float* __restrict__ bias) {
    __shared__ float t[64][65];
    __shared__ float bias_s[64];
    const int c0 = blockIdx.x * 64, r0 = blockIdx.y * 64;
    const int tx = threadIdx.x & 15, ty = threadIdx.x >> 4;
    if (threadIdx.x < 64) bias_s[threadIdx.x] = bias[c0 + threadIdx.x];
    __syncthreads();
#pragma unroll
    for (int k = 0; k < 4; ++k) {
        const int cl = ty + 16 * k;
        const __half2* p = (const __half2*)(src + (size_t)(c0 + cl) * NROWS + r0 + 4 * tx);
        __half2 a = p[0], b = p[1];
        const float bv = bias_s[cl];
        t[4 * tx + 0][cl] = __low2float(a)  + bv;
        t[4 * tx + 1][cl] = __high2float(a) + bv;
        t[4 * tx + 2][cl] = __low2float(b)  + bv;
        t[4 * tx + 3][cl] = __high2float(b) + bv;
    }
    __syncthreads();
#pragma unroll
    for (int k = 0; k < 4; ++k) {
        const int rl = ty + 16 * k;
        float4 w = make_float4(t[rl][4 * tx + 0], t[rl][4 * tx + 1],
                               t[rl][4 * tx + 2], t[rl][4 * tx + 3]);
        *(float4*)(dst + (size_t)(r0 + rl) * NFEAT + c0 + 4 * tx) = w;
    }
}

// ---------------------------------------------------------------------------
// MMA helpers
// ---------------------------------------------------------------------------
__device__ __forceinline__ void ldsm4(unsigned r[4], const __half* p) {
    unsigned a = (unsigned)__cvta_generic_to_shared(p);
    asm volatile("ldmatrix.sync.aligned.m8n8.x4.shared.b16 {%0,%1,%2,%3}, [%4];"
                 : "=r"(r[0]), "=r"(r[1]), "=r"(r[2]), "=r"(r[3]) : "r"(a));
}
__device__ __forceinline__ void ldsm4t(unsigned r[4], const __half* p) {
    unsigned a = (unsigned)__cvta_generic_to_shared(p);
    asm volatile("ldmatrix.sync.aligned.m8n8.x4.trans.shared.b16 {%0,%1,%2,%3}, [%4];"
                 : "=r"(r[0]), "=r"(r[1]), "=r"(r[2]), "=r"(r[3]) : "r"(a));
}
__device__ __forceinline__ void mma16816(float c[4], const unsigned a[4],
                                         unsigned b0, unsigned b1) {
    asm volatile("mma.sync.aligned.m16n8k16.row.col.f32.f16.f16.f32 "
                 "{%0,%1,%2,%3}, {%4,%5,%6,%7}, {%8,%9}, {%0,%1,%2,%3};"
                 : "+f"(c[0]), "+f"(c[1]), "+f"(c[2]), "+f"(c[3])
                 : "r"(a[0]), "r"(a[1]), "r"(a[2]), "r"(a[3]), "r"(b0), "r"(b1));
}

// ---------------------------------------------------------------------------
// GEMM stage (all fp16 I/O): D[n][r] = sum_k W[blk,n,k] * B[k][r]
//  stage 1: B rows = xt[(k*128+blk)],  stage 2: B rows = z[(blk*128+k)]
//  D rows = (n*128+blk).  cp.async double-buffered K chunks of 64.
// ---------------------------------------------------------------------------
__global__ void __launch_bounds__(256, 2)
gemm_k(__half* __restrict__ dst, const __half* __restrict__ bsrc,
       const __half* __restrict__ wimg, int stage) {
    extern __shared__ __half sh[];
    __half* wpl[2] = { sh,              sh + WCH + BCH };
    __half* bpl[2] = { sh + WCH,        sh + 2 * WCH + BCH };

    const int blk = blockIdx.y;
    const int r0  = blockIdx.x * 128;
    const int tid = threadIdx.x;

    const __half* wsrc = wimg + (size_t)blk * 16384;
    __half* D = dst + (size_t)blk * 4096;

    // ---- issue both K chunks via cp.async
#pragma unroll
    for (int kc = 0; kc < 2; ++kc) {
        const uint32_t wb = (uint32_t)__cvta_generic_to_shared(wpl[kc]);
        const uint32_t bb = (uint32_t)__cvta_generic_to_shared(bpl[kc]);
#pragma unroll
        for (int it = 0; it < 4; ++it) {           // W: 128n x 64k fp16
            int idx = it * 256 + tid;              // 1024 x 16B
            int n = idx >> 3, q = idx & 7;
            cp16(wb + (uint32_t)(n * LDWW + q * 8) * 2,
                 wsrc + kc * 8192 + n * 64 + q * 8);
        }
#pragma unroll
        for (int it = 0; it < 4; ++it) {           // B: 64k x 128r fp16
            int idx = it * 256 + tid;
            int k = idx >> 4, q = idx & 15;
            int krow = kc * 64 + k;
            size_t grow = (stage == 1) ? ((size_t)krow * 128 + blk)
                                       : ((size_t)blk * 128 + krow);
            cp16(bb + (uint32_t)(k * LDB + q * 8) * 2,
                 bsrc + grow * 4096 + r0 + q * 8);
        }
        CP_COMMIT();
    }

    const int wid = tid >> 5, lane = tid & 31;
    const int wm = (wid & 1) * 64;
    const int wr = (wid >> 1) * 32;
    const int lrow  = lane & 15;
    const int lcol8 = (lane >> 4) << 3;

    float acc[4][4][4];
#pragma unroll
    for (int a = 0; a < 4; ++a)
#pragma unroll
        for (int b = 0; b < 4; ++b)
#pragma unroll
            for (int c = 0; c < 4; ++c) acc[a][b][c] = 0.0f;

#pragma unroll
    for (int kc = 0; kc < 2; ++kc) {
        if (kc == 0) { CP_WAIT(1); } else { CP_WAIT(0); }
        __syncthreads();
        const __half* wsm = wpl[kc];
        const __half* bsm = bpl[kc];
#pragma unroll
        for (int k0 = 0; k0 < 64; k0 += 16) {
            unsigned Ah[4][4], Bh[2][4];
#pragma unroll
            for (int mt = 0; mt < 4; ++mt)
                ldsm4(Ah[mt], wsm + (wm + mt * 16 + lrow) * LDWW + k0 + lcol8);
#pragma unroll
            for (int h = 0; h < 2; ++h)
                ldsm4t(Bh[h], bsm + (k0 + lrow) * LDB + wr + h * 16 + lcol8);
#pragma unroll
            for (int mt = 0; mt < 4; ++mt)
#pragma unroll
                for (int rt = 0; rt < 4; ++rt) {
                    const int h = rt >> 1, p = (rt & 1) * 2;
                    mma16816(acc[mt][rt], Ah[mt], Bh[h][p], Bh[h][p + 1]);
                }
        }
    }

    // ---- epilogue: fp16 stores, rows strided DSTRIDE
    const int erow = lane >> 2;
    const int ecol = (lane & 3) * 2;
#pragma unroll
    for (int mt = 0; mt < 4; ++mt)
#pragma unroll
        for (int rt = 0; rt < 4; ++rt) {
            const int n0 = wm + mt * 16 + erow;
            const int rr = r0 + wr + rt * 8 + ecol;
            __half2 h01 = __floats2half2_rn(acc[mt][rt][0], acc[mt][rt][1]);
            __half2 h23 = __floats2half2_rn(acc[mt][rt][2], acc[mt][rt][3]);
            *(__half2*)(D + (size_t)n0 * DSTRIDE + rr)       = h01;
            *(__half2*)(D + (size_t)(n0 + 8) * DSTRIDE + rr) = h23;
        }
}

// ---------------------------------------------------------------------------
extern "C" void kernel_launch(void* const* d_in, const int* in_sizes, int n_in,
                              void* d_out, int out_size) {
    const float* x    = (const float*)d_in[0];
    const float* L    = (const float*)d_in[1];
    const float* R    = (const float*)d_in[2];
    const float* bias = (const float*)d_in[3];
    float* out = (float*)d_out;

    float *pA, *pB;
    cudaGetSymbolAddress((void**)&pA, g_bufA);
    cudaGetSymbolAddress((void**)&pB, g_bufB);
    __half* hA = (__half*)pA;
    __half* hB = (__half*)pB;
    __half* wh;
    cudaGetSymbolAddress((void**)&wh, g_wh);
    cudaFuncSetAttribute(gemm_k, cudaFuncAttributeMaxDynamicSharedMemorySize, SMEM_BYTES);

    // 0) weights -> fp16 chunk-major images
    prep_w_k<<<dim3(128, 2), 256>>>(L, R);
    // 1) xt[c][r] = fp16(x[r][c])
    t1_k<<<dim3(NFEAT / 64, NROWS / 64), 256>>>(hA, x);
    // 2) z[(n*128+b)][r] = fp16( sum_m L[b,n,m] * xt[(m*128+b)][r] )
    gemm_k<<<dim3(NROWS / 128, 128), 256, SMEM_BYTES>>>(hB, hA, wh, 1);
    // 3) out2[(i*128+j)][r] = fp16( sum_m R[j,i,m] * z[(j*128+m)][r] )
    gemm_k<<<dim3(NROWS / 128, 128), 256, SMEM_BYTES>>>(hA, hB, wh + (size_t)128 * 16384, 2);
    // 4) out[r][c] = out2[c][r] + bias[c]
    t2_k<<<dim3(NFEAT / 64, NROWS / 64), 256>>>(out, hA, bias);
}